// round 13
// baseline (speedup 1.0000x reference)
#include <cuda_runtime.h>
#include <math.h>

#define DD 4096
#define NF4 (DD / 4)          // 1024 float4 per row

__device__ float g_xk[DD], g_xv[DD], g_xr[DD];
__device__ float g_k[DD], g_v[DD], g_r[DD], g_rv[DD];

__device__ __forceinline__ float dot4(float4 a, float4 b) {
    float s = a.x * b.x;
    s = fmaf(a.y, b.y, s);
    s = fmaf(a.z, b.z, s);
    s = fmaf(a.w, b.w, s);
    return s;
}

// grid 16 x 64: one float4 per thread
__global__ void mix_kernel(const float* __restrict__ x,
                           const float* __restrict__ sxx,
                           const float* __restrict__ tmk,
                           const float* __restrict__ tmv,
                           const float* __restrict__ tmr) {
    int i = blockIdx.x * 64 + threadIdx.x;
    if (i >= NF4) return;
    float4 xi = ((const float4*)x)[i];
    float4 si = ((const float4*)sxx)[i];
    float4 k = ((const float4*)tmk)[i];
    float4 v = ((const float4*)tmv)[i];
    float4 r = ((const float4*)tmr)[i];
    float4 ok, ov, orr;
    ok.x = fmaf(xi.x - si.x, k.x, si.x);  ok.y = fmaf(xi.y - si.y, k.y, si.y);
    ok.z = fmaf(xi.z - si.z, k.z, si.z);  ok.w = fmaf(xi.w - si.w, k.w, si.w);
    ov.x = fmaf(xi.x - si.x, v.x, si.x);  ov.y = fmaf(xi.y - si.y, v.y, si.y);
    ov.z = fmaf(xi.z - si.z, v.z, si.z);  ov.w = fmaf(xi.w - si.w, v.w, si.w);
    orr.x = fmaf(xi.x - si.x, r.x, si.x); orr.y = fmaf(xi.y - si.y, r.y, si.y);
    orr.z = fmaf(xi.z - si.z, r.z, si.z); orr.w = fmaf(xi.w - si.w, r.w, si.w);
    ((float4*)g_xk)[i] = ok;
    ((float4*)g_xv)[i] = ov;
    ((float4*)g_xr)[i] = orr;
}

// Warp computes dots of TWO rows (A0, A1) against shared b.
// 4-deep batches: 12 loads in flight, b loaded once for both rows,
// 2 accumulators per row to shorten FMA chains.
__device__ __forceinline__ void row_pair_dot(const float4* __restrict__ A0,
                                             const float4* __restrict__ A1,
                                             const float4* __restrict__ B,
                                             int lane, float& out0, float& out1) {
    float s00 = 0.f, s01 = 0.f, s10 = 0.f, s11 = 0.f;
    #pragma unroll
    for (int t = 0; t < 8; t++) {
        float4 b[4], a0[4], a1[4];
        #pragma unroll
        for (int u = 0; u < 4; u++) {
            int j = lane + (t * 4 + u) * 32;
            b[u]  = __ldg(&B[j]);
            a0[u] = __ldcs(&A0[j]);
            a1[u] = __ldcs(&A1[j]);
        }
        s00 += dot4(a0[0], b[0]); s01 += dot4(a0[1], b[1]);
        s10 += dot4(a1[0], b[0]); s11 += dot4(a1[1], b[1]);
        s00 += dot4(a0[2], b[2]); s01 += dot4(a0[3], b[3]);
        s10 += dot4(a1[2], b[2]); s11 += dot4(a1[3], b[3]);
    }
    float s0 = s00 + s01, s1 = s10 + s11;
    #pragma unroll
    for (int o = 16; o; o >>= 1) {
        s0 += __shfl_xor_sync(0xffffffffu, s0, o);
        s1 += __shfl_xor_sync(0xffffffffu, s1, o);
    }
    out0 = s0; out1 = s1;
}

// one 1-warp block per (row-pair, matrix). grid = (DD/2, 3), block = 32
__global__ void __launch_bounds__(32) matvec3_kernel(
        const float* __restrict__ wk, const float* __restrict__ wv,
        const float* __restrict__ wr) {
    const int lane = threadIdx.x;
    const int r0   = blockIdx.x * 2;
    const int m    = blockIdx.y;

    const float* W = (m == 0) ? wk   : (m == 1) ? wv   : wr;
    const float* B = (m == 0) ? g_xk : (m == 1) ? g_xv : g_xr;

    float s0, s1;
    row_pair_dot((const float4*)(W + (size_t)r0 * DD),
                 (const float4*)(W + (size_t)(r0 + 1) * DD),
                 (const float4*)B, lane, s0, s1);

    if (lane == 0) {
        if (m == 0)      { g_k[r0] = s0; g_k[r0 + 1] = s1; }
        else if (m == 1) { g_v[r0] = s0; g_v[r0 + 1] = s1; }
        else {
            g_r[r0]     = 1.0f / (1.0f + expf(-s0));
            g_r[r0 + 1] = 1.0f / (1.0f + expf(-s1));
        }
    }
}

// grid 32 x 128. out: [y | x | new_aa | new_bb | new_pp]
__global__ void wkv_kernel(const float* __restrict__ x,
                           const float* __restrict__ aa,
                           const float* __restrict__ bb,
                           const float* __restrict__ pp,
                           const float* __restrict__ t_decay,
                           const float* __restrict__ t_first,
                           float* __restrict__ out) {
    int i = blockIdx.x * 128 + threadIdx.x;
    if (i >= DD) return;
    float k = g_k[i], v = g_v[i], r = g_r[i];
    float ppi = pp[i], aai = aa[i], bbi = bb[i];

    float ww = t_first[i] + k;
    float p  = fmaxf(ppi, ww);
    float e1 = expf(ppi - p);
    float e2 = expf(ww - p);
    float a  = fmaf(e1, aai, e2 * v);
    float b  = fmaf(e1, bbi, e2);
    g_rv[i]  = r * (a / b);

    float ww2 = ppi + t_decay[i];
    float p2  = fmaxf(ww2, k);
    float e1b = expf(ww2 - p2);
    float e2b = expf(k - p2);

    out[DD + i]     = x[i];
    out[2 * DD + i] = fmaf(e1b, aai, e2b * v);
    out[3 * DD + i] = fmaf(e1b, bbi, e2b);
    out[4 * DD + i] = p2;
}

// one 1-warp block per row-pair. grid = DD/2, block = 32
__global__ void __launch_bounds__(32) matvec_out_kernel(
        const float* __restrict__ wo, float* __restrict__ out) {
    const int lane = threadIdx.x;
    const int r0   = blockIdx.x * 2;

    float s0, s1;
    row_pair_dot((const float4*)(wo + (size_t)r0 * DD),
                 (const float4*)(wo + (size_t)(r0 + 1) * DD),
                 (const float4*)g_rv, lane, s0, s1);

    if (lane == 0) { out[r0] = s0; out[r0 + 1] = s1; }
}

extern "C" void kernel_launch(void* const* d_in, const int* in_sizes, int n_in,
                              void* d_out, int out_size) {
    const float* x       = (const float*)d_in[0];
    const float* sxx     = (const float*)d_in[1];
    const float* aa      = (const float*)d_in[2];
    const float* bb      = (const float*)d_in[3];
    const float* pp      = (const float*)d_in[4];
    const float* w_key   = (const float*)d_in[5];
    const float* w_val   = (const float*)d_in[6];
    const float* w_rec   = (const float*)d_in[7];
    const float* w_out   = (const float*)d_in[8];
    const float* t_decay = (const float*)d_in[9];
    const float* t_first = (const float*)d_in[10];
    const float* t_mix_k = (const float*)d_in[11];
    const float* t_mix_v = (const float*)d_in[12];
    const float* t_mix_r = (const float*)d_in[13];
    float* out = (float*)d_out;

    mix_kernel<<<16, 64>>>(x, sxx, t_mix_k, t_mix_v, t_mix_r);
    matvec3_kernel<<<dim3(DD / 2, 3), 32>>>(w_key, w_val, w_rec);
    wkv_kernel<<<32, 128>>>(x, aa, bb, pp, t_decay, t_first, out);
    matvec_out_kernel<<<DD / 2, 32>>>(w_out, out);
}